// round 13
// baseline (speedup 1.0000x reference)
#include <cuda_runtime.h>
#include <math.h>

#define BATCH 4
#define CDIM  64
#define KD    32
#define OD    64
#define NPIX  4096
#define KK    409
#define EPSF  1e-10f
#define LISTCAP 448
#define CANDCAP 1536
#define NBIN0   1024

// ---------------- scratch ----------------
__device__ __align__(16) float g_q[BATCH * KD * NPIX];           // [b][kd][n]
__device__ __align__(16) float g_k[BATCH * KD * NPIX];           // [b][kd][n]
__device__ __align__(16) float g_v[BATCH * NPIX * OD];           // [b][n][od]
__device__ __align__(16) float g_e[(size_t)BATCH * NPIX * NPIX]; // [b][i][j]

// ---------------- f32x2 helpers ----------------
__device__ __forceinline__ unsigned long long pack2(float a, float b) {
    unsigned long long r;
    asm("mov.b64 %0, {%1, %2};" : "=l"(r) : "f"(a), "f"(b));
    return r;
}
__device__ __forceinline__ void fma2(unsigned long long& d,
                                     unsigned long long a, unsigned long long b) {
    asm("fma.rn.f32x2 %0, %1, %2, %0;" : "+l"(d) : "l"(a), "l"(b));
}
__device__ __forceinline__ float2 unpack2(unsigned long long v) {
    float2 f;
    asm("mov.b64 {%0, %1}, %2;" : "=f"(f.x), "=f"(f.y) : "l"(v));
    return f;
}
__device__ __forceinline__ unsigned f2mono(float f) {
    unsigned u = __float_as_uint(f);
    return (u & 0x80000000u) ? ~u : (u | 0x80000000u);
}
__device__ __forceinline__ float mono2f(unsigned u) {
    unsigned v = (u & 0x80000000u) ? (u & 0x7fffffffu) : ~u;
    return __uint_as_float(v);
}
// transposed 1024-bin location: bin b -> (b&31)*32 + (b>>5)
__device__ __forceinline__ int hloc(unsigned bin) {
    return (int)(((bin & 31u) << 5) | (bin >> 5));
}

// ---------------- nop kernel: shifts the ncu capture slot ----------------
__global__ void nop_kernel() {}

// ---------------- kernel 0: fused QKV projection (fp32 V) ----------------
__global__ void __launch_bounds__(256, 4)
proj_kernel(const float* __restrict__ x,
            const float* __restrict__ Wq, const float* __restrict__ bq,
            const float* __restrict__ Wk, const float* __restrict__ bk,
            const float* __restrict__ Wv, const float* __restrict__ bv)
{
    __shared__ float xs[64 * 64];     // [c][p]
    __shared__ float Wall[128 * 64];  // rows 0-31 Wq, 32-63 Wk, 64-127 Wv
    __shared__ float ball[128];

    const int b  = blockIdx.x >> 6;
    const int n0 = (blockIdx.x & 63) * 64;
    const int t  = threadIdx.x;

    for (int i = t; i < 32 * 64; i += 256) Wall[i] = Wq[i];
    for (int i = t; i < 32 * 64; i += 256) Wall[32 * 64 + i] = Wk[i];
    for (int i = t; i < 64 * 64; i += 256) Wall[64 * 64 + i] = Wv[i];
    if (t < 32)        ball[t] = bq[t];
    else if (t < 64)   ball[t] = bk[t - 32];
    else if (t < 128)  ball[t] = bv[t - 64];

    const float* xb = x + (size_t)b * CDIM * NPIX;
    for (int i = t; i < CDIM * 64; i += 256) {
        int c = i >> 6, p = i & 63;
        xs[c * 64 + p] = xb[(size_t)c * NPIX + n0 + p];
    }
    __syncthreads();

    const int p = t & 63;
    const int h = t >> 6;

    if (h < 2) {
        const int ob = h * 32;
        float* dstbase = (h == 0) ? g_q : g_k;
        for (int oo = 0; oo < 32; oo++) {
            float acc = ball[ob + oo];
            const float* wr = Wall + (ob + oo) * 64;
            #pragma unroll 16
            for (int c = 0; c < 64; c++) acc = fmaf(wr[c], xs[c * 64 + p], acc);
            dstbase[((size_t)b * KD + oo) * NPIX + n0 + p] = acc;
        }
    } else {
        const int h2 = h - 2;
        float vacc[32];
        #pragma unroll
        for (int od = 0; od < 32; od++) vacc[od] = ball[64 + h2 * 32 + od];
        for (int c = 0; c < 64; c++) {
            float xv = xs[c * 64 + p];
            #pragma unroll
            for (int od = 0; od < 32; od++)
                vacc[od] = fmaf(Wall[(64 + h2 * 32 + od) * 64 + c], xv, vacc[od]);
        }
        float4* vd = (float4*)(g_v + ((size_t)b * NPIX + n0 + p) * OD + h2 * 32);
        #pragma unroll
        for (int q4 = 0; q4 < 8; q4++)
            vd[q4] = make_float4(vacc[4 * q4], vacc[4 * q4 + 1],
                                 vacc[4 * q4 + 2], vacc[4 * q4 + 3]);
    }
}

// ---------------- kernel 1: energy GEMM (R8-proven) ----------------
__global__ void __launch_bounds__(256, 2)
energy_kernel()
{
    __shared__ float Qs[32 * 128];   // [kd][ii]
    __shared__ float Ks[32 * 128];   // [kd][jj]

    const int b  = blockIdx.z;
    const int iT = blockIdx.y * 128;
    const int jT = blockIdx.x * 128;
    const int t  = threadIdx.x;

    const float4* qg = (const float4*)(g_q + (size_t)b * KD * NPIX);
    const float4* kg = (const float4*)(g_k + (size_t)b * KD * NPIX);
    for (int m = t; m < 1024; m += 256) {
        int kd = m >> 5, f = m & 31;
        ((float4*)Qs)[m] = qg[kd * (NPIX / 4) + (iT >> 2) + f];
        ((float4*)Ks)[m] = kg[kd * (NPIX / 4) + (jT >> 2) + f];
    }
    __syncthreads();

    const int tx = t & 15, ty = t >> 4;

    unsigned long long acc[8][4];
    #pragma unroll
    for (int ri = 0; ri < 8; ri++)
        #pragma unroll
        for (int c = 0; c < 4; c++) acc[ri][c] = 0ull;

    #pragma unroll 1
    for (int kd = 0; kd < KD; kd++) {
        const float4* qa = (const float4*)(Qs + kd * 128 + ty * 8);
        float4 a0 = qa[0], a1 = qa[1];
        const ulonglong2* kb = (const ulonglong2*)(Ks + kd * 128 + tx * 8);
        ulonglong2 b01 = kb[0], b23 = kb[1];
        float av[8] = {a0.x, a0.y, a0.z, a0.w, a1.x, a1.y, a1.z, a1.w};
        #pragma unroll
        for (int ri = 0; ri < 8; ri++) {
            unsigned long long aa = pack2(av[ri], av[ri]);
            fma2(acc[ri][0], b01.x, aa);
            fma2(acc[ri][1], b01.y, aa);
            fma2(acc[ri][2], b23.x, aa);
            fma2(acc[ri][3], b23.y, aa);
        }
    }

    float* eb = g_e + ((size_t)b * NPIX + iT) * NPIX + jT;
    #pragma unroll
    for (int ri = 0; ri < 8; ri++) {
        float2 p0 = unpack2(acc[ri][0]), p1 = unpack2(acc[ri][1]);
        float2 p2 = unpack2(acc[ri][2]), p3 = unpack2(acc[ri][3]);
        float4* dst = (float4*)(eb + (size_t)(ty * 8 + ri) * NPIX + tx * 8);
        dst[0] = make_float4(p0.x, p0.y, p1.x, p1.y);
        dst[1] = make_float4(p2.x, p2.y, p3.x, p3.y);
    }
}

// ---------------- kernel 2: per-row select + softmax + PV ----------------
// grid BATCH*NPIX CTAs, 128 threads, ~18KB smem, reg-capped for 12 CTAs/SM.
__global__ void __launch_bounds__(128, 12)
select_pv_kernel(const float* __restrict__ x, const float* __restrict__ gamma,
                 float* __restrict__ out)
{
    __shared__ int            hist[NBIN0];       // 4KB; transposed layout in pass 1
    __shared__ unsigned       cdm[CANDCAP];      // 6KB candidate mono keys
    __shared__ unsigned short cdi[CANDCAP];      // 3KB candidate indices
    __shared__ float          wl[LISTCAP];
    __shared__ int            il[LISTCAP];
    __shared__ float          obuf[4][OD];
    __shared__ float          zsum_s;
    __shared__ int            cnt_s, ccnt_s, rem_s;
    __shared__ unsigned       pfx_s, b0_s;

    const int bi = blockIdx.x;
    const int b  = bi >> 12;
    const int i  = bi & (NPIX - 1);
    const int t    = threadIdx.x;
    const int lane = t & 31;
    const int warp = t >> 5;

    if (t == 0) { cnt_s = 0; ccnt_s = 0; zsum_s = 0.f; }
    for (int m = t; m < NBIN0; m += 128) hist[m] = 0;
    __syncthreads();

    const float4* er = (const float4*)(g_e + ((size_t)b * NPIX + i) * NPIX);

    // ---- pass 1: 10-bit histogram, TRANSPOSED layout (conflict-free scan) ----
    #pragma unroll
    for (int k = 0; k < 8; k++) {
        float4 v4 = er[t + 128 * k];
        atomicAdd(&hist[hloc(f2mono(v4.x) >> 22)], 1);
        atomicAdd(&hist[hloc(f2mono(v4.y) >> 22)], 1);
        atomicAdd(&hist[hloc(f2mono(v4.z) >> 22)], 1);
        atomicAdd(&hist[hloc(f2mono(v4.w) >> 22)], 1);
    }
    __syncthreads();

    // ---- b0 scan (warp 0): lane l owns bin group [32l, 32l+31] ----
    // transposed layout: bin 32l+u2 lives at hist[u2*32 + l]  (lane stride 1)
    if (warp == 0) {
        int lsum = 0;
        #pragma unroll
        for (int u2 = 0; u2 < 32; u2++) lsum += hist[u2 * 32 + lane];
        // inclusive SUFFIX scan across lanes (groups ascend with lane)
        int incl = lsum;
        #pragma unroll
        for (int o = 1; o < 32; o <<= 1) {
            int vv = __shfl_down_sync(0xffffffffu, incl, o);
            if (lane < 32 - o) incl += vv;
        }
        int above = incl - lsum;   // count in groups strictly above this one
        if (above < KK && KK <= incl) {
            // walk bins within group from top (u2=31) down
            int cum = above, bsel = 32 * lane + 31;
            #pragma unroll
            for (int u2 = 31; u2 >= 0; u2--) {
                int c = hist[u2 * 32 + lane];
                if (cum + c >= KK) { bsel = 32 * lane + u2; break; }
                cum += c;
            }
            b0_s  = (unsigned)bsel;
            rem_s = KK - cum;
        }
    }
    __syncthreads();

    const unsigned B0 = b0_s;

    // ---- pass 2: single merged candidate collection (bin >= B0) ----
    #pragma unroll
    for (int k = 0; k < 8; k++) {
        const int f = t + 128 * k;
        float4 v4 = er[f];
        float vv[4] = {v4.x, v4.y, v4.z, v4.w};
        #pragma unroll
        for (int c = 0; c < 4; c++) {
            unsigned u = f2mono(vv[c]);
            bool cand = ((u >> 22) >= B0);
            unsigned bc = __ballot_sync(0xffffffffu, cand);
            if (cand) {
                int ldr = __ffs(bc) - 1, base = 0;
                if (lane == ldr) base = atomicAdd(&ccnt_s, __popc(bc));
                base = __shfl_sync(bc, base, ldr);
                int pos = base + __popc(bc & ((1u << lane) - 1u));
                if (pos < CANDCAP) { cdm[pos] = u; cdi[pos] = (unsigned short)(4 * f + c); }
            }
        }
    }
    __syncthreads();

    // ---- radix over boundary-bin candidates: remaining 22 bits {8,8,6} ----
    float zpart = 0.f;
    {
        int C = ccnt_s; if (C > CANDCAP) C = CANDCAP;
        const int Cpad = (C + 127) & ~127;
        unsigned pfx = B0;
        int rem = rem_s;

        #pragma unroll
        for (int pass = 0; pass < 3; pass++) {
            const int nb     = (pass == 2) ? 64 : 256;
            const int shift  = (pass == 0) ? 14 : (pass == 1) ? 6 : 0;
            const int pshift = (pass == 0) ? 22 : (pass == 1) ? 14 : 6;
            const int nbits  = (pass == 2) ? 6 : 8;
            for (int q = t; q < nb; q += 128) hist[q] = 0;
            __syncthreads();
            for (int q = t; q < Cpad; q += 128) {
                bool valid = (q < C);
                unsigned u = valid ? cdm[q] : 0u;
                if (valid && ((u >> pshift) == pfx))
                    atomicAdd(&hist[(u >> shift) & (unsigned)(nb - 1)], 1);
            }
            __syncthreads();
            if (warp == 0) {
                const int per = nb / 32;
                int bb0 = nb - 1 - per * lane;
                int lsum = 0;
                for (int u2 = 0; u2 < per; u2++) lsum += hist[bb0 - u2];
                int incl = lsum;
                #pragma unroll
                for (int o = 1; o < 32; o <<= 1) {
                    int vv = __shfl_up_sync(0xffffffffu, incl, o);
                    if (lane >= o) incl += vv;
                }
                int above = incl - lsum;
                if (above < rem && rem <= incl) {
                    int cum = above, bsel = bb0;
                    for (int u2 = 0; u2 < per; u2++) {
                        int c = hist[bb0 - u2];
                        if (cum + c >= rem) { bsel = bb0 - u2; break; }
                        cum += c;
                    }
                    pfx_s = (pfx << nbits) | (unsigned)bsel;
                    rem_s = rem - cum;
                }
            }
            __syncthreads();
            pfx = pfx_s;
            rem = rem_s;
        }

        // ---- final scan: key >= exact threshold T; weights rel. to T ----
        const unsigned T = pfx;
        const float m = mono2f(T);   // shift-invariant softmax reference
        for (int q = t; q < Cpad; q += 128) {
            bool valid = (q < C);
            unsigned u = valid ? cdm[q] : 0u;
            bool sel = valid && (u >= T);
            unsigned bs = __ballot_sync(0xffffffffu, sel);
            if (sel) {
                float w = __expf(mono2f(u) - m);
                zpart += w;
                int ldr = __ffs(bs) - 1, base = 0;
                if (lane == ldr) base = atomicAdd(&cnt_s, __popc(bs));
                base = __shfl_sync(bs, base, ldr);
                int pos = base + __popc(bs & ((1u << lane) - 1u));
                if (pos < LISTCAP) { il[pos] = (int)cdi[q]; wl[pos] = w; }
            }
        }
    }
    #pragma unroll
    for (int o = 16; o; o >>= 1) zpart += __shfl_xor_sync(0xffffffffu, zpart, o);
    if (lane == 0) atomicAdd(&zsum_s, zpart);
    __syncthreads();

    // ---- PV: 4 warps split list; 2 j's per step (16 lanes each);
    //      lane loads float4 (4 od) and does 2x FFMA2 ----
    {
        int n = cnt_s; if (n > LISTCAP) n = LISTCAP;
        const float4* vb = (const float4*)(g_v + (size_t)b * NPIX * OD);
        const int hsel = lane >> 4;     // 0: j_a, 1: j_b
        const int lq   = lane & 15;     // od chunk: 4*lq .. 4*lq+3

        int quarter = (n + 3) >> 2;
        int start = warp * quarter;
        int end   = start + quarter; if (end > n) end = n;

        unsigned long long a01 = 0ull, a23 = 0ull;
        int tix = start;
        for (; tix + 2 <= end; tix += 2) {
            int   jj = il[tix + hsel];
            float w  = wl[tix + hsel];
            unsigned long long ww = pack2(w, w);
            float4 v4 = vb[(size_t)jj * 16 + lq];
            fma2(a01, pack2(v4.x, v4.y), ww);
            fma2(a23, pack2(v4.z, v4.w), ww);
        }
        if (tix < end && hsel == 0) {   // odd tail: lanes 0-15 only
            int   jj = il[tix];
            float w  = wl[tix];
            unsigned long long ww = pack2(w, w);
            float4 v4 = vb[(size_t)jj * 16 + lq];
            fma2(a01, pack2(v4.x, v4.y), ww);
            fma2(a23, pack2(v4.z, v4.w), ww);
        }
        float2 p01 = unpack2(a01), p23 = unpack2(a23);
        p01.x += __shfl_down_sync(0xffffffffu, p01.x, 16);
        p01.y += __shfl_down_sync(0xffffffffu, p01.y, 16);
        p23.x += __shfl_down_sync(0xffffffffu, p23.x, 16);
        p23.y += __shfl_down_sync(0xffffffffu, p23.y, 16);
        if (hsel == 0)
            *(float4*)&obuf[warp][4 * lq] = make_float4(p01.x, p01.y, p23.x, p23.y);
    }
    __syncthreads();

    // ---- epilogue: 64 threads, one channel each ----
    if (t < CDIM) {
        const float g = gamma[0];
        float a = obuf[0][t] + obuf[1][t] + obuf[2][t] + obuf[3][t];
        const float invZ = 1.f / (zsum_s + EPSF);
        const size_t oix = ((size_t)b * CDIM + t) * NPIX + i;
        out[oix] = g * a * invZ + x[oix];
    }
}

// ---------------- launch ----------------
extern "C" void kernel_launch(void* const* d_in, const int* in_sizes, int n_in,
                              void* d_out, int out_size)
{
    const float* x     = (const float*)d_in[0];
    const float* Wq    = (const float*)d_in[1];
    const float* bq    = (const float*)d_in[2];
    const float* Wk    = (const float*)d_in[3];
    const float* bk    = (const float*)d_in[4];
    const float* Wv    = (const float*)d_in[5];
    const float* bv    = (const float*)d_in[6];
    const float* gamma = (const float*)d_in[7];
    float* out = (float*)d_out;

    (void)in_sizes; (void)n_in; (void)out_size;

    nop_kernel<<<1, 32>>>();   // shifts ncu capture slot onto select

    proj_kernel<<<BATCH * 64, 256>>>(x, Wq, bq, Wk, bk, Wv, bv);

    dim3 egrid(NPIX / 128, NPIX / 128, BATCH);
    energy_kernel<<<egrid, 256>>>();

    select_pv_kernel<<<BATCH * NPIX, 128>>>(x, gamma, out);
}

// round 14
// speedup vs baseline: 1.0762x; 1.0762x over previous
#include <cuda_runtime.h>
#include <math.h>

#define BATCH 4
#define CDIM  64
#define KD    32
#define OD    64
#define NPIX  4096
#define KK    409
#define EPSF  1e-10f
#define LISTCAP 448
#define CANDCAP 1536
#define NBIN0   1024

// ---------------- scratch ----------------
__device__ __align__(16) float g_q[BATCH * KD * NPIX];           // [b][kd][n]
__device__ __align__(16) float g_k[BATCH * KD * NPIX];           // [b][kd][n]
__device__ __align__(16) float g_v[BATCH * NPIX * OD];           // [b][n][od]
__device__ __align__(16) float g_e[(size_t)BATCH * NPIX * NPIX]; // [b][i][j]

// ---------------- f32x2 helpers ----------------
__device__ __forceinline__ unsigned long long pack2(float a, float b) {
    unsigned long long r;
    asm("mov.b64 %0, {%1, %2};" : "=l"(r) : "f"(a), "f"(b));
    return r;
}
__device__ __forceinline__ void fma2(unsigned long long& d,
                                     unsigned long long a, unsigned long long b) {
    asm("fma.rn.f32x2 %0, %1, %2, %0;" : "+l"(d) : "l"(a), "l"(b));
}
__device__ __forceinline__ float2 unpack2(unsigned long long v) {
    float2 f;
    asm("mov.b64 {%0, %1}, %2;" : "=f"(f.x), "=f"(f.y) : "l"(v));
    return f;
}
__device__ __forceinline__ unsigned f2mono(float f) {
    unsigned u = __float_as_uint(f);
    return (u & 0x80000000u) ? ~u : (u | 0x80000000u);
}
__device__ __forceinline__ float mono2f(unsigned u) {
    unsigned v = (u & 0x80000000u) ? (u & 0x7fffffffu) : ~u;
    return __uint_as_float(v);
}

// ---------------- nop kernel: shifts the ncu capture slot ----------------
__global__ void nop_kernel() {}

// ---------------- kernel 0: fused QKV projection (fp32 V) ----------------
__global__ void __launch_bounds__(256, 4)
proj_kernel(const float* __restrict__ x,
            const float* __restrict__ Wq, const float* __restrict__ bq,
            const float* __restrict__ Wk, const float* __restrict__ bk,
            const float* __restrict__ Wv, const float* __restrict__ bv)
{
    __shared__ float xs[64 * 64];     // [c][p]
    __shared__ float Wall[128 * 64];  // rows 0-31 Wq, 32-63 Wk, 64-127 Wv
    __shared__ float ball[128];

    const int b  = blockIdx.x >> 6;
    const int n0 = (blockIdx.x & 63) * 64;
    const int t  = threadIdx.x;

    for (int i = t; i < 32 * 64; i += 256) Wall[i] = Wq[i];
    for (int i = t; i < 32 * 64; i += 256) Wall[32 * 64 + i] = Wk[i];
    for (int i = t; i < 64 * 64; i += 256) Wall[64 * 64 + i] = Wv[i];
    if (t < 32)        ball[t] = bq[t];
    else if (t < 64)   ball[t] = bk[t - 32];
    else if (t < 128)  ball[t] = bv[t - 64];

    const float* xb = x + (size_t)b * CDIM * NPIX;
    for (int i = t; i < CDIM * 64; i += 256) {
        int c = i >> 6, p = i & 63;
        xs[c * 64 + p] = xb[(size_t)c * NPIX + n0 + p];
    }
    __syncthreads();

    const int p = t & 63;
    const int h = t >> 6;

    if (h < 2) {
        const int ob = h * 32;
        float* dstbase = (h == 0) ? g_q : g_k;
        for (int oo = 0; oo < 32; oo++) {
            float acc = ball[ob + oo];
            const float* wr = Wall + (ob + oo) * 64;
            #pragma unroll 16
            for (int c = 0; c < 64; c++) acc = fmaf(wr[c], xs[c * 64 + p], acc);
            dstbase[((size_t)b * KD + oo) * NPIX + n0 + p] = acc;
        }
    } else {
        const int h2 = h - 2;
        float vacc[32];
        #pragma unroll
        for (int od = 0; od < 32; od++) vacc[od] = ball[64 + h2 * 32 + od];
        for (int c = 0; c < 64; c++) {
            float xv = xs[c * 64 + p];
            #pragma unroll
            for (int od = 0; od < 32; od++)
                vacc[od] = fmaf(Wall[(64 + h2 * 32 + od) * 64 + c], xv, vacc[od]);
        }
        float4* vd = (float4*)(g_v + ((size_t)b * NPIX + n0 + p) * OD + h2 * 32);
        #pragma unroll
        for (int q4 = 0; q4 < 8; q4++)
            vd[q4] = make_float4(vacc[4 * q4], vacc[4 * q4 + 1],
                                 vacc[4 * q4 + 2], vacc[4 * q4 + 3]);
    }
}

// ---------------- kernel 1: energy GEMM (R8-proven) ----------------
__global__ void __launch_bounds__(256, 2)
energy_kernel()
{
    __shared__ float Qs[32 * 128];   // [kd][ii]
    __shared__ float Ks[32 * 128];   // [kd][jj]

    const int b  = blockIdx.z;
    const int iT = blockIdx.y * 128;
    const int jT = blockIdx.x * 128;
    const int t  = threadIdx.x;

    const float4* qg = (const float4*)(g_q + (size_t)b * KD * NPIX);
    const float4* kg = (const float4*)(g_k + (size_t)b * KD * NPIX);
    for (int m = t; m < 1024; m += 256) {
        int kd = m >> 5, f = m & 31;
        ((float4*)Qs)[m] = qg[kd * (NPIX / 4) + (iT >> 2) + f];
        ((float4*)Ks)[m] = kg[kd * (NPIX / 4) + (jT >> 2) + f];
    }
    __syncthreads();

    const int tx = t & 15, ty = t >> 4;

    unsigned long long acc[8][4];
    #pragma unroll
    for (int ri = 0; ri < 8; ri++)
        #pragma unroll
        for (int c = 0; c < 4; c++) acc[ri][c] = 0ull;

    #pragma unroll 1
    for (int kd = 0; kd < KD; kd++) {
        const float4* qa = (const float4*)(Qs + kd * 128 + ty * 8);
        float4 a0 = qa[0], a1 = qa[1];
        const ulonglong2* kb = (const ulonglong2*)(Ks + kd * 128 + tx * 8);
        ulonglong2 b01 = kb[0], b23 = kb[1];
        float av[8] = {a0.x, a0.y, a0.z, a0.w, a1.x, a1.y, a1.z, a1.w};
        #pragma unroll
        for (int ri = 0; ri < 8; ri++) {
            unsigned long long aa = pack2(av[ri], av[ri]);
            fma2(acc[ri][0], b01.x, aa);
            fma2(acc[ri][1], b01.y, aa);
            fma2(acc[ri][2], b23.x, aa);
            fma2(acc[ri][3], b23.y, aa);
        }
    }

    float* eb = g_e + ((size_t)b * NPIX + iT) * NPIX + jT;
    #pragma unroll
    for (int ri = 0; ri < 8; ri++) {
        float2 p0 = unpack2(acc[ri][0]), p1 = unpack2(acc[ri][1]);
        float2 p2 = unpack2(acc[ri][2]), p3 = unpack2(acc[ri][3]);
        float4* dst = (float4*)(eb + (size_t)(ty * 8 + ri) * NPIX + tx * 8);
        dst[0] = make_float4(p0.x, p0.y, p1.x, p1.y);
        dst[1] = make_float4(p2.x, p2.y, p3.x, p3.y);
    }
}

// ---------------- kernel 2: per-row select + softmax + PV ----------------
// grid BATCH*NPIX CTAs, 128 threads, ~19KB smem, reg-capped for 12 CTAs/SM.
__global__ void __launch_bounds__(128, 12)
select_pv_kernel(const float* __restrict__ x, const float* __restrict__ gamma,
                 float* __restrict__ out)
{
    __shared__ int            hist[NBIN0];       // 4KB (natural layout; reused in radix)
    __shared__ int            s8[128];           // stage-A partial sums (8 bins each)
    __shared__ unsigned       cdm[CANDCAP];      // 6KB candidate mono keys
    __shared__ unsigned short cdi[CANDCAP];      // 3KB candidate indices
    __shared__ float          wl[LISTCAP];
    __shared__ int            il[LISTCAP];
    __shared__ float          obuf[4][OD];
    __shared__ float          zsum_s;
    __shared__ int            cnt_s, ccnt_s, rem_s;
    __shared__ unsigned       pfx_s, b0_s;

    const int bi = blockIdx.x;
    const int b  = bi >> 12;
    const int i  = bi & (NPIX - 1);
    const int t    = threadIdx.x;
    const int lane = t & 31;
    const int warp = t >> 5;

    if (t == 0) { cnt_s = 0; ccnt_s = 0; zsum_s = 0.f; }
    for (int m = t; m < NBIN0; m += 128) hist[m] = 0;
    __syncthreads();

    const float4* er = (const float4*)(g_e + ((size_t)b * NPIX + i) * NPIX);

    // ---- pass 1: 10-bit histogram (natural layout, plain smem atomics) ----
    #pragma unroll
    for (int k = 0; k < 8; k++) {
        float4 v4 = er[t + 128 * k];
        atomicAdd(&hist[f2mono(v4.x) >> 22], 1);
        atomicAdd(&hist[f2mono(v4.y) >> 22], 1);
        atomicAdd(&hist[f2mono(v4.z) >> 22], 1);
        atomicAdd(&hist[f2mono(v4.w) >> 22], 1);
    }
    __syncthreads();

    // ---- stage A: 128 threads fold 8 bins each (one-shot, cheap) ----
    {
        int acc = 0;
        const int base = 8 * t;
        #pragma unroll
        for (int u2 = 0; u2 < 8; u2++) acc += hist[base + u2];
        s8[t] = acc;
    }
    __syncthreads();

    // ---- stage B: warp 0 finds boundary bin b0 ----
    if (warp == 0) {
        const int g0 = 4 * lane;                  // lane covers bins [32l, 32l+31]
        int a0 = s8[g0], a1 = s8[g0 + 1], a2 = s8[g0 + 2], a3 = s8[g0 + 3];
        int lsum = (a0 + a1) + (a2 + a3);
        // inclusive SUFFIX scan across lanes (higher lane = higher bins)
        int incl = lsum;
        #pragma unroll
        for (int o = 1; o < 32; o <<= 1) {
            int vv = __shfl_down_sync(0xffffffffu, incl, o);
            if (lane < 32 - o) incl += vv;
        }
        int above = incl - lsum;                  // count in bins > 32l+31
        if (above < KK && KK <= incl) {
            int cum = above;
            int subsum[4] = {a0, a1, a2, a3};
            int sub = 3;
            #pragma unroll
            for (int sdown = 3; sdown >= 0; sdown--) {
                if (cum + subsum[sdown] >= KK) { sub = sdown; break; }
                cum += subsum[sdown];
            }
            int bbase = 8 * (g0 + sub);
            int bsel = bbase + 7;
            #pragma unroll
            for (int u2 = 7; u2 >= 0; u2--) {
                int c = hist[bbase + u2];
                if (cum + c >= KK) { bsel = bbase + u2; break; }
                cum += c;
            }
            b0_s  = (unsigned)bsel;
            rem_s = KK - cum;
        }
    }
    __syncthreads();

    const unsigned B0 = b0_s;

    // ---- pass 2: single merged candidate collection (bin >= B0) ----
    #pragma unroll
    for (int k = 0; k < 8; k++) {
        const int f = t + 128 * k;
        float4 v4 = er[f];
        float vv[4] = {v4.x, v4.y, v4.z, v4.w};
        #pragma unroll
        for (int c = 0; c < 4; c++) {
            unsigned u = f2mono(vv[c]);
            bool cand = ((u >> 22) >= B0);
            unsigned bc = __ballot_sync(0xffffffffu, cand);
            if (cand) {
                int ldr = __ffs(bc) - 1, base = 0;
                if (lane == ldr) base = atomicAdd(&ccnt_s, __popc(bc));
                base = __shfl_sync(bc, base, ldr);
                int pos = base + __popc(bc & ((1u << lane) - 1u));
                if (pos < CANDCAP) { cdm[pos] = u; cdi[pos] = (unsigned short)(4 * f + c); }
            }
        }
    }
    __syncthreads();

    // ---- radix over boundary-bin candidates: remaining 22 bits {8,8,6} ----
    float zpart = 0.f;
    {
        int C = ccnt_s; if (C > CANDCAP) C = CANDCAP;
        const int Cpad = (C + 127) & ~127;
        unsigned pfx = B0;
        int rem = rem_s;

        #pragma unroll
        for (int pass = 0; pass < 3; pass++) {
            const int nb     = (pass == 2) ? 64 : 256;
            const int shift  = (pass == 0) ? 14 : (pass == 1) ? 6 : 0;
            const int pshift = (pass == 0) ? 22 : (pass == 1) ? 14 : 6;
            const int nbits  = (pass == 2) ? 6 : 8;
            for (int q = t; q < nb; q += 128) hist[q] = 0;
            __syncthreads();
            for (int q = t; q < Cpad; q += 128) {
                bool valid = (q < C);
                unsigned u = valid ? cdm[q] : 0u;
                if (valid && ((u >> pshift) == pfx))
                    atomicAdd(&hist[(u >> shift) & (unsigned)(nb - 1)], 1);
            }
            __syncthreads();
            if (warp == 0) {
                const int per = nb / 32;
                int bb0 = nb - 1 - per * lane;
                int lsum = 0;
                for (int u2 = 0; u2 < per; u2++) lsum += hist[bb0 - u2];
                int incl = lsum;
                #pragma unroll
                for (int o = 1; o < 32; o <<= 1) {
                    int vv = __shfl_up_sync(0xffffffffu, incl, o);
                    if (lane >= o) incl += vv;
                }
                int above = incl - lsum;
                if (above < rem && rem <= incl) {
                    int cum = above, bsel = bb0;
                    for (int u2 = 0; u2 < per; u2++) {
                        int c = hist[bb0 - u2];
                        if (cum + c >= rem) { bsel = bb0 - u2; break; }
                        cum += c;
                    }
                    pfx_s = (pfx << nbits) | (unsigned)bsel;
                    rem_s = rem - cum;
                }
            }
            __syncthreads();
            pfx = pfx_s;
            rem = rem_s;
        }

        // ---- final scan: key >= exact threshold T; weights rel. to T ----
        const unsigned T = pfx;
        const float m = mono2f(T);   // shift-invariant softmax reference
        for (int q = t; q < Cpad; q += 128) {
            bool valid = (q < C);
            unsigned u = valid ? cdm[q] : 0u;
            bool sel = valid && (u >= T);
            unsigned bs = __ballot_sync(0xffffffffu, sel);
            if (sel) {
                float w = __expf(mono2f(u) - m);
                zpart += w;
                int ldr = __ffs(bs) - 1, base = 0;
                if (lane == ldr) base = atomicAdd(&cnt_s, __popc(bs));
                base = __shfl_sync(bs, base, ldr);
                int pos = base + __popc(bs & ((1u << lane) - 1u));
                if (pos < LISTCAP) { il[pos] = (int)cdi[q]; wl[pos] = w; }
            }
        }
    }
    #pragma unroll
    for (int o = 16; o; o >>= 1) zpart += __shfl_xor_sync(0xffffffffu, zpart, o);
    if (lane == 0) atomicAdd(&zsum_s, zpart);
    __syncthreads();

    // ---- PV: 4 warps split list; 2 j's per step (16 lanes each);
    //      lane loads float4 (4 od) and does 2x FFMA2 ----
    {
        int n = cnt_s; if (n > LISTCAP) n = LISTCAP;
        const float4* vb = (const float4*)(g_v + (size_t)b * NPIX * OD);
        const int hsel = lane >> 4;     // 0: j_a, 1: j_b
        const int lq   = lane & 15;     // od chunk: 4*lq .. 4*lq+3

        int quarter = (n + 3) >> 2;
        int start = warp * quarter;
        int end   = start + quarter; if (end > n) end = n;

        unsigned long long a01 = 0ull, a23 = 0ull;
        int tix = start;
        for (; tix + 2 <= end; tix += 2) {
            int   jj = il[tix + hsel];
            float w  = wl[tix + hsel];
            unsigned long long ww = pack2(w, w);
            float4 v4 = vb[(size_t)jj * 16 + lq];
            fma2(a01, pack2(v4.x, v4.y), ww);
            fma2(a23, pack2(v4.z, v4.w), ww);
        }
        if (tix < end && hsel == 0) {   // odd tail: lanes 0-15 only
            int   jj = il[tix];
            float w  = wl[tix];
            unsigned long long ww = pack2(w, w);
            float4 v4 = vb[(size_t)jj * 16 + lq];
            fma2(a01, pack2(v4.x, v4.y), ww);
            fma2(a23, pack2(v4.z, v4.w), ww);
        }
        float2 p01 = unpack2(a01), p23 = unpack2(a23);
        p01.x += __shfl_down_sync(0xffffffffu, p01.x, 16);
        p01.y += __shfl_down_sync(0xffffffffu, p01.y, 16);
        p23.x += __shfl_down_sync(0xffffffffu, p23.x, 16);
        p23.y += __shfl_down_sync(0xffffffffu, p23.y, 16);
        if (hsel == 0)
            *(float4*)&obuf[warp][4 * lq] = make_float4(p01.x, p01.y, p23.x, p23.y);
    }
    __syncthreads();

    // ---- epilogue: 64 threads, one channel each ----
    if (t < CDIM) {
        const float g = gamma[0];
        float a = obuf[0][t] + obuf[1][t] + obuf[2][t] + obuf[3][t];
        const float invZ = 1.f / (zsum_s + EPSF);
        const size_t oix = ((size_t)b * CDIM + t) * NPIX + i;
        out[oix] = g * a * invZ + x[oix];
    }
}

// ---------------- launch ----------------
extern "C" void kernel_launch(void* const* d_in, const int* in_sizes, int n_in,
                              void* d_out, int out_size)
{
    const float* x     = (const float*)d_in[0];
    const float* Wq    = (const float*)d_in[1];
    const float* bq    = (const float*)d_in[2];
    const float* Wk    = (const float*)d_in[3];
    const float* bk    = (const float*)d_in[4];
    const float* Wv    = (const float*)d_in[5];
    const float* bv    = (const float*)d_in[6];
    const float* gamma = (const float*)d_in[7];
    float* out = (float*)d_out;

    (void)in_sizes; (void)n_in; (void)out_size;

    nop_kernel<<<1, 32>>>();   // shifts ncu capture slot onto select

    proj_kernel<<<BATCH * 64, 256>>>(x, Wq, bq, Wk, bk, Wv, bv);

    dim3 egrid(NPIX / 128, NPIX / 128, BATCH);
    energy_kernel<<<egrid, 256>>>();

    select_pv_kernel<<<BATCH * NPIX, 128>>>(x, gamma, out);
}